// round 16
// baseline (speedup 1.0000x reference)
#include <cuda_runtime.h>
#include <math.h>
#include <stdint.h>

#define D_TOT 320
#define DZ    64
#define DX    256
#define DKK   256
#define HID   16
#define BATCH 1024
#define NEG   0.01f
#define HALF_LOG2PI 0.91893853320467274f

#define NWIN  80               // 80 windows of 4 j
// smem (floats): UW 3*4608 = 13824 | MHhi 5120 | MHlo 5120 => 24064 floats
#define UW_F   0
#define MHI_F  13824
#define MLO_F  18944
#define SMEMF  24064
#define DYN_SMEM (SMEMF * 4)   // 96,256 B (occ 2)

// device scratch
__device__ float g_E[D_TOT * D_TOT];            // exp(-mask_param) [j][k]
__device__ float g_Wfh[DKK * NWIN * 2 * 32];    // W0 hi, fragment order [k'][w][hh][lane]
__device__ float g_Wfl[DKK * NWIN * 2 * 32];    // W0 lo residual
__device__ float g_sT[D_TOT * BATCH];           // all_var transposed [j][b]
__device__ float g_accum;
__device__ unsigned int g_done;

__device__ __forceinline__ float lrelu(float v) { return fmaxf(v, NEG * v); }

__device__ __forceinline__ float tf32r(float f) {
    uint32_t r; asm("cvt.rna.tf32.f32 %0, %1;" : "=r"(r) : "f"(f));
    return __uint_as_float(r);
}
__device__ __forceinline__ void cp_async16(uint32_t dst, const void* src) {
    asm volatile("cp.async.cg.shared.global [%0], [%1], 16;" :: "r"(dst), "l"(src));
}
__device__ __forceinline__ void mma4(float* c, uint32_t a0, uint32_t a1, uint32_t b0) {
    asm volatile("mma.sync.aligned.m16n8k4.row.col.f32.tf32.tf32.f32 "
                 "{%0,%1,%2,%3}, {%4,%5}, {%6}, {%0,%1,%2,%3};"
                 : "+f"(c[0]), "+f"(c[1]), "+f"(c[2]), "+f"(c[3])
                 : "r"(a0), "r"(a1), "r"(b0));
}

// ---------------------------------------------------------------------------
// Init: E; W0 -> hi/lo tf32 split in FRAGMENT order [k'][w][hh][lane]
// (j = w*4 + (lane&3), h = hh*8 + (lane>>2), diag zeroed); s transpose; std.
// Bound = 256*80*2*32 = 1,310,720 covers everything.
// ---------------------------------------------------------------------------
__global__ void init_kernel(const float* __restrict__ mp,
                            const float* __restrict__ W0,
                            const float* __restrict__ x,
                            const float* __restrict__ z,
                            const float* __restrict__ logvar,
                            float* __restrict__ out) {
    int i = blockIdx.x * blockDim.x + threadIdx.x;
    if (i < DKK * NWIN * 2 * 32) {
        int lane = i & 31;
        int hh   = (i >> 5) & 1;
        int w    = (i >> 6) % NWIN;
        int kp   = i / (NWIN * 2 * 32);
        int j    = w * 4 + (lane & 3);
        int h    = hh * 8 + (lane >> 2);
        int kg   = DZ + kp;
        float wv = (j == kg) ? 0.0f : W0[((size_t)kg * D_TOT + j) * HID + h];
        float wh = tf32r(wv);
        g_Wfh[i] = wh;
        g_Wfl[i] = tf32r(wv - wh);
    }
    if (i < D_TOT * D_TOT) g_E[i] = expf(-mp[i]);
    if (i < D_TOT * BATCH) {
        int b = i / D_TOT;
        int j = i % D_TOT;
        float s = (j < DZ) ? z[b * DZ + j] : x[b * DX + (j - DZ)];
        g_sT[(size_t)j * BATCH + b] = s;
    }
    if (i < D_TOT) out[1 + BATCH * D_TOT + i] = expf(0.5f * logvar[i]);
    if (i == 0) { g_accum = 0.0f; g_done = 0u; }
}

// ---------------------------------------------------------------------------
// Latent path: k < 64 (fp32, unchanged)
// ---------------------------------------------------------------------------
__global__ void latent_kernel(const float* __restrict__ z,
                              const float* __restrict__ u,
                              const float* __restrict__ W0,
                              const float* __restrict__ b0,
                              const float* __restrict__ W1,
                              const float* __restrict__ b1,
                              const float* __restrict__ W2,
                              const float* __restrict__ b2,
                              const float* __restrict__ logvar,
                              float* __restrict__ out) {
    int tid = blockIdx.x * blockDim.x + threadIdx.x;
    int k = tid & (DZ - 1);
    int b = tid >> 6;

    float uu = u[((size_t)b * D_TOT + k) * D_TOT + k];
    float E  = g_E[k * D_TOT + k];
    float s  = z[b * DZ + k];
    float m = __fdividef(uu * s, fmaf(1.0f - uu, E, uu));

    float h1v[HID];
#pragma unroll
    for (int g = 0; g < HID; g++) h1v[g] = b1[k * HID + g];
#pragma unroll
    for (int h = 0; h < HID; h++) {
        float a = lrelu(fmaf(m, W0[((size_t)k * D_TOT + k) * HID + h], b0[k * HID + h]));
        const float* w1r = W1 + (k * HID + h) * HID;
#pragma unroll
        for (int g = 0; g < HID; g++) h1v[g] = fmaf(a, w1r[g], h1v[g]);
    }
    float mu = b2[k];
#pragma unroll
    for (int h = 0; h < HID; h++) mu = fmaf(lrelu(h1v[h]), W2[k * HID + h], mu);

    out[1 + (size_t)b * D_TOT + k] = mu;

    float logstd = 0.5f * logvar[k];
    float istd = __expf(-logstd);
    float diff = (s - mu) * istd;
    float lp = fmaf(-0.5f * diff, diff, -logstd - HALF_LOG2PI);
#pragma unroll
    for (int o = 16; o > 0; o >>= 1) lp += __shfl_down_sync(0xffffffffu, lp, o);
    if ((threadIdx.x & 31) == 0) atomicAdd(&g_accum, lp);
}

// ---------------------------------------------------------------------------
// Dense: 3xTF32 mma.m16n8k4. Block = 32 k x 32 b. u in 4-j windows (ring 3);
// m split hi/lo into smem; 48 mma.k4 per warp per window; B frags coalesced
// from fragment-order tables.
// ---------------------------------------------------------------------------
__global__ void __launch_bounds__(256, 2)
dense_kernel(const float* __restrict__ x,
             const float* __restrict__ u,
             const float* __restrict__ b0,
             const float* __restrict__ W1,
             const float* __restrict__ b1,
             const float* __restrict__ W2,
             const float* __restrict__ b2,
             const float* __restrict__ logvar,
             float* __restrict__ out) {
    extern __shared__ float dynsm[];
    float* uw  = dynsm + UW_F;
    float* Mhi = dynsm + MHI_F;
    float* Mlo = dynsm + MLO_F;

    int tid  = threadIdx.x;
    int lane = tid & 31;
    int warp = tid >> 5;
    int kx   = blockIdx.x;             // k-tile (8)
    int by   = blockIdx.y;             // b-tile (32)
    int kb0  = DZ + kx * 32;

    uint32_t uw_b = (uint32_t)__cvta_generic_to_shared(uw);

    // cp.async mapping: b = tid>>3, kc = tid&7, j = chunk i
    int cb = tid >> 3;
    int ckc = tid & 7;
    const float* ubase = u + ((size_t)(by * 32 + cb) * D_TOT) * D_TOT
                           + kb0 + ckc * 4;
    uint32_t dstt = uw_b + (uint32_t)((cb * 36 + ckc * 4) << 2);

    // m-pass roles: b = tid&31, jloc = (tid>>5)&3, kh = tid>>7
    int mb = tid & 31;
    int mj = (tid >> 5) & 3;
    int mkh = tid >> 7;

    // acc C-frags: [i(4k)][st(2)][hh(2)][4]
    float acc[4][2][2][4];
#pragma unroll
    for (int i = 0; i < 4; i++)
#pragma unroll
        for (int st = 0; st < 2; st++)
#pragma unroll
            for (int hh = 0; hh < 2; hh++)
#pragma unroll
                for (int r = 0; r < 4; r++) acc[i][st][hh][r] = 0.0f;

    // prologue: fill 2 windows
#pragma unroll
    for (int w0 = 0; w0 < 2; w0++) {
        const float* sp = ubase + (size_t)w0 * 1280;
        uint32_t dp = dstt + (w0 % 3) * 18432u;
#pragma unroll
        for (int i = 0; i < 4; i++)
            cp_async16(dp + i * 4608u, sp + i * D_TOT);
        asm volatile("cp.async.commit_group;");
    }

    for (int w = 0; w < NWIN; w++) {
        if (w + 2 < NWIN) {
            const float* sp = ubase + (size_t)(w + 2) * 1280;
            uint32_t dp = dstt + ((w + 2) % 3) * 18432u;
#pragma unroll
            for (int i = 0; i < 4; i++)
                cp_async16(dp + i * 4608u, sp + i * D_TOT);
            asm volatile("cp.async.commit_group;");
        }
        if (w < NWIN - 2)       asm volatile("cp.async.wait_group 2;");
        else if (w == NWIN - 2) asm volatile("cp.async.wait_group 1;");
        else                    asm volatile("cp.async.wait_group 0;");
        __syncthreads();        // u ready + M free (prev window's mma done)

        // ---- B-frag loads (coalesced, fragment-order tables) ----
        uint32_t Bh[4][2], Bl[4][2];
#pragma unroll
        for (int i = 0; i < 4; i++) {
            size_t base = (((size_t)(kx * 32 + warp * 4 + i) * NWIN + w) * 2) * 32 + lane;
#pragma unroll
            for (int hh = 0; hh < 2; hh++) {
                Bh[i][hh] = __float_as_uint(__ldg(g_Wfh + base + hh * 32));
                Bl[i][hh] = __float_as_uint(__ldg(g_Wfl + base + hh * 32));
            }
        }

        // ---- m-pass: compute m hi/lo for window w ----
        {
            int jg = w * 4 + mj;
            float s = __ldg(g_sT + (size_t)jg * BATCH + by * 32 + mb);
            const float* Ep = g_E + jg * D_TOT + kb0 + mkh * 16;
            const float* up = uw + (w % 3) * 4608 + mj * 1152 + mb * 36 + mkh * 16;
            float* Mjh = Mhi + mj * 40 + mb;
            float* Mjl = Mlo + mj * 40 + mb;
#pragma unroll
            for (int q = 0; q < 4; q++) {
                float4 uu = *(const float4*)(up + q * 4);
                float4 Eq = *(const float4*)(Ep + q * 4);
                int kk = mkh * 16 + q * 4;
                float mv, mh;
                mv = __fdividef(uu.x * s, fmaf(uu.x, 1.0f - Eq.x, Eq.x));
                mh = tf32r(mv); Mjh[(kk + 0) * 160] = mh; Mjl[(kk + 0) * 160] = tf32r(mv - mh);
                mv = __fdividef(uu.y * s, fmaf(uu.y, 1.0f - Eq.y, Eq.y));
                mh = tf32r(mv); Mjh[(kk + 1) * 160] = mh; Mjl[(kk + 1) * 160] = tf32r(mv - mh);
                mv = __fdividef(uu.z * s, fmaf(uu.z, 1.0f - Eq.z, Eq.z));
                mh = tf32r(mv); Mjh[(kk + 2) * 160] = mh; Mjl[(kk + 2) * 160] = tf32r(mv - mh);
                mv = __fdividef(uu.w * s, fmaf(uu.w, 1.0f - Eq.w, Eq.w));
                mh = tf32r(mv); Mjh[(kk + 3) * 160] = mh; Mjl[(kk + 3) * 160] = tf32r(mv - mh);
            }
        }
        __syncthreads();        // M ready

        // ---- mma-pass: 3xTF32 compensation ----
#pragma unroll
        for (int i = 0; i < 4; i++) {
            int kl = warp * 4 + i;
            const float* Mah = Mhi + kl * 160 + (lane & 3) * 40;
            const float* Mal = Mlo + kl * 160 + (lane & 3) * 40;
#pragma unroll
            for (int st = 0; st < 2; st++) {
                int bidx = st * 16 + (lane >> 2);
                uint32_t ah0 = __float_as_uint(Mah[bidx]);
                uint32_t ah1 = __float_as_uint(Mah[bidx + 8]);
                uint32_t al0 = __float_as_uint(Mal[bidx]);
                uint32_t al1 = __float_as_uint(Mal[bidx + 8]);
#pragma unroll
                for (int hh = 0; hh < 2; hh++) {
                    mma4(acc[i][st][hh], ah0, ah1, Bh[i][hh]);
                    mma4(acc[i][st][hh], ah0, ah1, Bl[i][hh]);
                    mma4(acc[i][st][hh], al0, al1, Bh[i][hh]);
                }
            }
        }
    }
    __syncthreads();            // all mma reads done before Mep overwrites

    // ---- epilogue: transpose C-frags via smem, per-(b,k) MLP tail ----
    float* Mep = dynsm;   // [b32][k32][20]
    {
        int r0 = lane >> 2;
        int c0 = 2 * (lane & 3);
#pragma unroll
        for (int i = 0; i < 4; i++) {
            int kl = warp * 4 + i;
#pragma unroll
            for (int st = 0; st < 2; st++)
#pragma unroll
                for (int hh = 0; hh < 2; hh++) {
                    float* p = Mep + (st * 16 + r0) * 640 + kl * 20 + hh * 8 + c0;
                    p[0] = acc[i][st][hh][0];
                    p[1] = acc[i][st][hh][1];
                    p[8 * 640]     = acc[i][st][hh][2];
                    p[8 * 640 + 1] = acc[i][st][hh][3];
                }
        }
    }
    __syncthreads();

    int kl = tid & 31;
    int kg = DZ + kx * 32 + kl;
    float logstd = 0.5f * logvar[kg];
    float istd = __expf(-logstd);
    float lpsum = 0.0f;

#pragma unroll
    for (int ii = 0; ii < 4; ii++) {
        int b = (tid >> 5) + ii * 8;
        int bg = by * 32 + b;

        float a0[HID];
        {
            const float* mp_ = Mep + b * 640 + kl * 20;
#pragma unroll
            for (int q = 0; q < 4; q++) {
                float4 v = *(const float4*)(mp_ + q * 4);
                a0[q * 4 + 0] = v.x; a0[q * 4 + 1] = v.y;
                a0[q * 4 + 2] = v.z; a0[q * 4 + 3] = v.w;
            }
        }
#pragma unroll
        for (int h = 0; h < HID; h++) a0[h] += b0[kg * HID + h];

        float h1v[HID];
#pragma unroll
        for (int g = 0; g < HID; g++) h1v[g] = b1[kg * HID + g];
#pragma unroll
        for (int h = 0; h < HID; h++) {
            float a = lrelu(a0[h]);
            const float4* w1p = (const float4*)(W1 + ((size_t)kg * HID + h) * HID);
            float4 r0 = w1p[0], r1 = w1p[1], r2 = w1p[2], r3 = w1p[3];
            float wrg[HID] = {r0.x, r0.y, r0.z, r0.w, r1.x, r1.y, r1.z, r1.w,
                              r2.x, r2.y, r2.z, r2.w, r3.x, r3.y, r3.z, r3.w};
#pragma unroll
            for (int g = 0; g < HID; g++) h1v[g] = fmaf(a, wrg[g], h1v[g]);
        }
        float mu = b2[kg];
#pragma unroll
        for (int h = 0; h < HID; h++) mu = fmaf(lrelu(h1v[h]), W2[kg * HID + h], mu);

        out[1 + (size_t)bg * D_TOT + kg] = mu;

        float sv = x[(size_t)bg * DX + (kg - DZ)];
        float diff = (sv - mu) * istd;
        lpsum += fmaf(-0.5f * diff, diff, -logstd - HALF_LOG2PI);
    }

#pragma unroll
    for (int o = 16; o > 0; o >>= 1) lpsum += __shfl_down_sync(0xffffffffu, lpsum, o);
    if (lane == 0) atomicAdd(&g_accum, lpsum);

    __syncthreads();
    if (tid == 0) {
        __threadfence();
        unsigned int n = atomicAdd(&g_done, 1u);
        if (n == gridDim.x * gridDim.y - 1) {
            float total = atomicAdd(&g_accum, 0.0f);
            out[0] = total * (1.0f / (float)BATCH);
        }
    }
}

// ---------------------------------------------------------------------------
extern "C" void kernel_launch(void* const* d_in, const int* in_sizes, int n_in,
                              void* d_out, int out_size) {
    const float* x      = (const float*)d_in[0];
    const float* z      = (const float*)d_in[1];
    const float* u      = (const float*)d_in[2];
    const float* mp     = (const float*)d_in[3];
    const float* W0     = (const float*)d_in[4];
    const float* b0     = (const float*)d_in[5];
    const float* W1     = (const float*)d_in[6];
    const float* b1     = (const float*)d_in[7];
    const float* W2     = (const float*)d_in[8];
    const float* b2     = (const float*)d_in[9];
    const float* logvar = (const float*)d_in[10];
    float* out = (float*)d_out;

    static int attr_done = 0;
    if (!attr_done) {
        cudaFuncSetAttribute(dense_kernel,
                             cudaFuncAttributeMaxDynamicSharedMemorySize, DYN_SMEM);
        attr_done = 1;
    }

    {
        int total = DKK * NWIN * 2 * 32;   // 1,310,720 covers all init work
        init_kernel<<<(total + 255) / 256, 256>>>(mp, W0, x, z, logvar, out);
    }
    latent_kernel<<<(BATCH * DZ) / 256, 256>>>(z, u, W0, b0, W1, b1, W2, b2, logvar, out);
    {
        dim3 grid(8, 32);   // 256 blocks — single wave at occupancy 2
        dense_kernel<<<grid, 256, DYN_SMEM>>>(x, u, b0, W1, b1, W2, b2, logvar, out);
    }
}

// round 17
// speedup vs baseline: 1.1499x; 1.1499x over previous
#include <cuda_runtime.h>
#include <math.h>
#include <stdint.h>

#define D_TOT 320
#define DZ    64
#define DX    256
#define DKK   256
#define HID   16
#define BATCH 1024
#define NEG   0.01f
#define HALF_LOG2PI 0.91893853320467274f

#define NWIN  80               // 80 windows of 4 j
#define RING  4                // u ring depth (warp-private)
// UW: RING * 8 warps * 544 floats (entry = [j4][b32][k4], j-stride 136) = 17408
// Mep epilogue reuse needs 20480 floats -> DYN = 20480 floats
#define ENTRYF 544
#define JSTRIDE 136
#define DYN_SMEM (20480 * 4)   // 81,920 B (occ 2)

// device scratch
__device__ __align__(16) float g_E[D_TOT * D_TOT];   // exp(-mask_param) [j][k]
__device__ float2 g_Wf2[DKK * NWIN * 2 * 32];        // (hi,lo) tf32 W0, fragment order
__device__ float g_sT[D_TOT * BATCH];                // all_var transposed [j][b]
__device__ float g_accum;
__device__ unsigned int g_done;

__device__ __forceinline__ float lrelu(float v) { return fmaxf(v, NEG * v); }

__device__ __forceinline__ float tf32r(float f) {
    uint32_t r; asm("cvt.rna.tf32.f32 %0, %1;" : "=r"(r) : "f"(f));
    return __uint_as_float(r);
}
__device__ __forceinline__ void cp_async16(uint32_t dst, const void* src) {
    asm volatile("cp.async.cg.shared.global [%0], [%1], 16;" :: "r"(dst), "l"(src));
}
__device__ __forceinline__ void mma4(float* c, float a0, float a1, float b0) {
    asm volatile("mma.sync.aligned.m16n8k4.row.col.f32.tf32.tf32.f32 "
                 "{%0,%1,%2,%3}, {%4,%5}, {%6}, {%0,%1,%2,%3};"
                 : "+f"(c[0]), "+f"(c[1]), "+f"(c[2]), "+f"(c[3])
                 : "r"(__float_as_uint(a0)), "r"(__float_as_uint(a1)),
                   "r"(__float_as_uint(b0)));
}

// ---------------------------------------------------------------------------
// Init: E; W0 -> (hi,lo) tf32 float2 table in FRAGMENT order [k'][w][hh][lane]
// (j = w*4 + (lane&3), h = hh*8 + (lane>>2), diag zeroed); s transpose; std.
// ---------------------------------------------------------------------------
__global__ void init_kernel(const float* __restrict__ mp,
                            const float* __restrict__ W0,
                            const float* __restrict__ x,
                            const float* __restrict__ z,
                            const float* __restrict__ logvar,
                            float* __restrict__ out) {
    int i = blockIdx.x * blockDim.x + threadIdx.x;
    if (i < DKK * NWIN * 2 * 32) {
        int lane = i & 31;
        int hh   = (i >> 5) & 1;
        int w    = (i >> 6) % NWIN;
        int kp   = i / (NWIN * 2 * 32);
        int j    = w * 4 + (lane & 3);
        int h    = hh * 8 + (lane >> 2);
        int kg   = DZ + kp;
        float wv = (j == kg) ? 0.0f : W0[((size_t)kg * D_TOT + j) * HID + h];
        float wh = tf32r(wv);
        g_Wf2[i] = make_float2(wh, tf32r(wv - wh));
    }
    if (i < D_TOT * D_TOT) g_E[i] = expf(-mp[i]);
    if (i < D_TOT * BATCH) {
        int b = i / D_TOT;
        int j = i % D_TOT;
        float s = (j < DZ) ? z[b * DZ + j] : x[b * DX + (j - DZ)];
        g_sT[(size_t)j * BATCH + b] = s;
    }
    if (i < D_TOT) out[1 + BATCH * D_TOT + i] = expf(0.5f * logvar[i]);
    if (i == 0) { g_accum = 0.0f; g_done = 0u; }
}

// ---------------------------------------------------------------------------
// Latent path: k < 64 (fp32, unchanged)
// ---------------------------------------------------------------------------
__global__ void latent_kernel(const float* __restrict__ z,
                              const float* __restrict__ u,
                              const float* __restrict__ W0,
                              const float* __restrict__ b0,
                              const float* __restrict__ W1,
                              const float* __restrict__ b1,
                              const float* __restrict__ W2,
                              const float* __restrict__ b2,
                              const float* __restrict__ logvar,
                              float* __restrict__ out) {
    int tid = blockIdx.x * blockDim.x + threadIdx.x;
    int k = tid & (DZ - 1);
    int b = tid >> 6;

    float uu = u[((size_t)b * D_TOT + k) * D_TOT + k];
    float E  = g_E[k * D_TOT + k];
    float s  = z[b * DZ + k];
    float m = __fdividef(uu * s, fmaf(1.0f - uu, E, uu));

    float h1v[HID];
#pragma unroll
    for (int g = 0; g < HID; g++) h1v[g] = b1[k * HID + g];
#pragma unroll
    for (int h = 0; h < HID; h++) {
        float a = lrelu(fmaf(m, W0[((size_t)k * D_TOT + k) * HID + h], b0[k * HID + h]));
        const float* w1r = W1 + (k * HID + h) * HID;
#pragma unroll
        for (int g = 0; g < HID; g++) h1v[g] = fmaf(a, w1r[g], h1v[g]);
    }
    float mu = b2[k];
#pragma unroll
    for (int h = 0; h < HID; h++) mu = fmaf(lrelu(h1v[h]), W2[k * HID + h], mu);

    out[1 + (size_t)b * D_TOT + k] = mu;

    float logstd = 0.5f * logvar[k];
    float istd = __expf(-logstd);
    float diff = (s - mu) * istd;
    float lp = fmaf(-0.5f * diff, diff, -logstd - HALF_LOG2PI);
#pragma unroll
    for (int o = 16; o > 0; o >>= 1) lp += __shfl_down_sync(0xffffffffu, lp, o);
    if ((threadIdx.x & 31) == 0) atomicAdd(&g_accum, lp);
}

// ---------------------------------------------------------------------------
// Dense: warp-independent 3xTF32 mma. Warp owns 4 k x 32 b; u warp-private
// cp.async ring-4 [j4][b32][k4]; m computed in registers straight into mma
// A-fragments. NO smem M, NO in-loop barriers.
// ---------------------------------------------------------------------------
__global__ void __launch_bounds__(256, 2)
dense_kernel(const float* __restrict__ x,
             const float* __restrict__ u,
             const float* __restrict__ b0,
             const float* __restrict__ W1,
             const float* __restrict__ b1,
             const float* __restrict__ W2,
             const float* __restrict__ b2,
             const float* __restrict__ logvar,
             float* __restrict__ out) {
    extern __shared__ float dynsm[];
    float* uw = dynsm;                 // RING*8*544 floats

    int tid  = threadIdx.x;
    int lane = tid & 31;
    int warp = tid >> 5;
    int kx   = blockIdx.x;             // k-tile (8)
    int by   = blockIdx.y;             // b-tile (32)
    int kb0  = DZ + kx * 32;
    int kq   = kb0 + warp * 4;         // this warp's global k quad start
    int kpq  = kx * 32 + warp * 4;     // k' quad (table index)

    uint32_t uw_b = (uint32_t)__cvta_generic_to_shared(uw);
    int jl = lane & 3;                 // this thread's j within window
    int bl = lane >> 2;                // b row base

    // cp.async: lane stages b = lane, all 4 j, 16B (warp's k quad)
    const float* usrc = u + ((size_t)(by * 32 + lane) * D_TOT) * D_TOT + kq;
    uint32_t wslot0 = uw_b + (uint32_t)((warp * ENTRYF + lane * 4) << 2);

    float acc[4][2][2][4];
#pragma unroll
    for (int i = 0; i < 4; i++)
#pragma unroll
        for (int st = 0; st < 2; st++)
#pragma unroll
            for (int hh = 0; hh < 2; hh++)
#pragma unroll
                for (int r = 0; r < 4; r++) acc[i][st][hh][r] = 0.0f;

    // prologue: windows 0..2
#pragma unroll
    for (int w0 = 0; w0 < 3; w0++) {
        uint32_t dp = wslot0 + (uint32_t)(w0 * 8 * ENTRYF * 4);
#pragma unroll
        for (int j = 0; j < 4; j++)
            cp_async16(dp + (uint32_t)(j * JSTRIDE * 4),
                       usrc + (size_t)(w0 * 4 + j) * D_TOT);
        asm volatile("cp.async.commit_group;");
    }

    for (int w = 0; w < NWIN; w++) {
        // issue w+3 (ring slot reuse is warp-local-safe), always commit
        if (w + 3 < NWIN) {
            uint32_t dp = wslot0 + (uint32_t)((((w + 3) & 3) * 8 * ENTRYF) * 4);
#pragma unroll
            for (int j = 0; j < 4; j++)
                cp_async16(dp + (uint32_t)(j * JSTRIDE * 4),
                           usrc + (size_t)((w + 3) * 4 + j) * D_TOT);
        }
        asm volatile("cp.async.commit_group;");

        // L2/L1-hot loads issued before the wait
        float4 Ev = *(const float4*)(g_E + (size_t)(w * 4 + jl) * D_TOT + kq);
        float sreg[4];
#pragma unroll
        for (int t = 0; t < 4; t++)
            sreg[t] = __ldg(g_sT + (size_t)(w * 4 + jl) * BATCH + by * 32 + bl + 8 * t);
        float2 Bf[4][2];
#pragma unroll
        for (int i = 0; i < 4; i++) {
            size_t base = (((size_t)(kpq + i) * NWIN + w) * 2) * 32 + lane;
            Bf[i][0] = __ldg(g_Wf2 + base);
            Bf[i][1] = __ldg(g_Wf2 + base + 32);
        }

        asm volatile("cp.async.wait_group 3;");

        // u for this thread's 4 b-rows: [j=jl][b=bl+8t][k0..3]
        const float* ent = uw + ((w & 3) * 8 + warp) * ENTRYF + jl * JSTRIDE;
        float4 uv[4];
#pragma unroll
        for (int t = 0; t < 4; t++)
            uv[t] = *(const float4*)(ent + (bl + 8 * t) * 4);

#pragma unroll
        for (int i = 0; i < 4; i++) {
            float Ei = (i == 0) ? Ev.x : (i == 1) ? Ev.y : (i == 2) ? Ev.z : Ev.w;
            float e1 = 1.0f - Ei;
            float mh[4], ml[4];
#pragma unroll
            for (int t = 0; t < 4; t++) {
                float uu = (i == 0) ? uv[t].x : (i == 1) ? uv[t].y
                         : (i == 2) ? uv[t].z : uv[t].w;
                float mv = __fdividef(uu * sreg[t], fmaf(uu, e1, Ei));
                mh[t] = tf32r(mv);
                ml[t] = tf32r(mv - mh[t]);
            }
#pragma unroll
            for (int st = 0; st < 2; st++) {
                float a0 = mh[st * 2], a1 = mh[st * 2 + 1];
                float l0 = ml[st * 2], l1 = ml[st * 2 + 1];
#pragma unroll
                for (int hh = 0; hh < 2; hh++) {
                    mma4(acc[i][st][hh], a0, a1, Bf[i][hh].x);
                    mma4(acc[i][st][hh], a0, a1, Bf[i][hh].y);
                    mma4(acc[i][st][hh], l0, l1, Bf[i][hh].x);
                }
            }
        }
    }
    __syncthreads();   // all warps done with uw before Mep reuse

    // ---- epilogue: transpose C-frags via smem, per-(b,k) MLP tail ----
    float* Mep = dynsm;   // [b32][k32][20]
    {
        int r0 = lane >> 2;
        int c0 = 2 * (lane & 3);
#pragma unroll
        for (int i = 0; i < 4; i++) {
            int kl = warp * 4 + i;
#pragma unroll
            for (int st = 0; st < 2; st++)
#pragma unroll
                for (int hh = 0; hh < 2; hh++) {
                    float* p = Mep + (st * 16 + r0) * 640 + kl * 20 + hh * 8 + c0;
                    p[0] = acc[i][st][hh][0];
                    p[1] = acc[i][st][hh][1];
                    p[8 * 640]     = acc[i][st][hh][2];
                    p[8 * 640 + 1] = acc[i][st][hh][3];
                }
        }
    }
    __syncthreads();

    int kl = tid & 31;
    int kg = DZ + kx * 32 + kl;
    float logstd = 0.5f * logvar[kg];
    float istd = __expf(-logstd);
    float lpsum = 0.0f;

#pragma unroll
    for (int ii = 0; ii < 4; ii++) {
        int b = (tid >> 5) + ii * 8;
        int bg = by * 32 + b;

        float a0[HID];
        {
            const float* mp_ = Mep + b * 640 + kl * 20;
#pragma unroll
            for (int q = 0; q < 4; q++) {
                float4 v = *(const float4*)(mp_ + q * 4);
                a0[q * 4 + 0] = v.x; a0[q * 4 + 1] = v.y;
                a0[q * 4 + 2] = v.z; a0[q * 4 + 3] = v.w;
            }
        }
#pragma unroll
        for (int h = 0; h < HID; h++) a0[h] += b0[kg * HID + h];

        float h1v[HID];
#pragma unroll
        for (int g = 0; g < HID; g++) h1v[g] = b1[kg * HID + g];
#pragma unroll
        for (int h = 0; h < HID; h++) {
            float a = lrelu(a0[h]);
            const float4* w1p = (const float4*)(W1 + ((size_t)kg * HID + h) * HID);
            float4 r0 = w1p[0], r1 = w1p[1], r2 = w1p[2], r3 = w1p[3];
            float wrg[HID] = {r0.x, r0.y, r0.z, r0.w, r1.x, r1.y, r1.z, r1.w,
                              r2.x, r2.y, r2.z, r2.w, r3.x, r3.y, r3.z, r3.w};
#pragma unroll
            for (int g = 0; g < HID; g++) h1v[g] = fmaf(a, wrg[g], h1v[g]);
        }
        float mu = b2[kg];
#pragma unroll
        for (int h = 0; h < HID; h++) mu = fmaf(lrelu(h1v[h]), W2[kg * HID + h], mu);

        out[1 + (size_t)bg * D_TOT + kg] = mu;

        float sv = x[(size_t)bg * DX + (kg - DZ)];
        float diff = (sv - mu) * istd;
        lpsum += fmaf(-0.5f * diff, diff, -logstd - HALF_LOG2PI);
    }

#pragma unroll
    for (int o = 16; o > 0; o >>= 1) lpsum += __shfl_down_sync(0xffffffffu, lpsum, o);
    if (lane == 0) atomicAdd(&g_accum, lpsum);

    __syncthreads();
    if (tid == 0) {
        __threadfence();
        unsigned int n = atomicAdd(&g_done, 1u);
        if (n == gridDim.x * gridDim.y - 1) {
            float total = atomicAdd(&g_accum, 0.0f);
            out[0] = total * (1.0f / (float)BATCH);
        }
    }
}

// ---------------------------------------------------------------------------
extern "C" void kernel_launch(void* const* d_in, const int* in_sizes, int n_in,
                              void* d_out, int out_size) {
    const float* x      = (const float*)d_in[0];
    const float* z      = (const float*)d_in[1];
    const float* u      = (const float*)d_in[2];
    const float* mp     = (const float*)d_in[3];
    const float* W0     = (const float*)d_in[4];
    const float* b0     = (const float*)d_in[5];
    const float* W1     = (const float*)d_in[6];
    const float* b1     = (const float*)d_in[7];
    const float* W2     = (const float*)d_in[8];
    const float* b2     = (const float*)d_in[9];
    const float* logvar = (const float*)d_in[10];
    float* out = (float*)d_out;

    static int attr_done = 0;
    if (!attr_done) {
        cudaFuncSetAttribute(dense_kernel,
                             cudaFuncAttributeMaxDynamicSharedMemorySize, DYN_SMEM);
        attr_done = 1;
    }

    {
        int total = DKK * NWIN * 2 * 32;   // 1,310,720 covers all init work
        init_kernel<<<(total + 255) / 256, 256>>>(mp, W0, x, z, logvar, out);
    }
    latent_kernel<<<(BATCH * DZ) / 256, 256>>>(z, u, W0, b0, W1, b1, W2, b2, logvar, out);
    {
        dim3 grid(8, 32);   // 256 blocks — single wave at occupancy 2
        dense_kernel<<<grid, 256, DYN_SMEM>>>(x, u, b0, W1, b1, W2, b2, logvar, out);
    }
}